// round 7
// baseline (speedup 1.0000x reference)
#include <cuda_runtime.h>
#include <cstdint>

// Shapes (fixed):
//   x_main: [1, T=128, M=512, K=256] fp32
//   x_aux : [K=256, T=128, Da=256]   fp32
//   W     : [Da=256, E=512]          fp32
//   b     : [E=512]                  fp32
//   out   : [1,T,M,E,1] = [128,512,512] fp32
//
// R4 structure (best known: 186.6us) with occupancy raised: warp tile 32x32
// (acc 32 regs), CTA tile 128x64, 8 warps (4m x 2n), launch_bounds(256,3)
// -> 3 CTAs/SM = 24 warps (was 2 CTAs/16 warps, RF-capped by 64-reg acc).
//
// Stage 1 (per t): scratch[t][e][k] = relu( sum_d W[d][e]*x_aux[k][t][d] + b[e] )
//   M=e(512), N=k(256), red=d.  A = W (pre-rounded tf32, natural [d][e] smem,
//   transposed at fragment gather), B = x_aux rows (LDG+cvt+STS).
// Stage 2 (per t): out[t][m][e] = sum_k x_main[t][m][k] * scratch[t][e][k]
//   M=m(512), N=e(512), red=k.  A = x_main (LDG+cvt+STS), B = scratch
//   (tf32-rounded by stage-1 epilogue, cp.async).
// All values rna-rounded to tf32 exactly once (numerics identical to R3/R4).

__device__ __align__(16) float g_scratch[128 * 512 * 256];  // [T][E][K], 64 MB
__device__ __align__(16) float g_Wtf32[256 * 512];          // W pre-rounded

static constexpr int S_A = 18432;   // A region per buffer: 128*36*4 (>= 32*136*4 W tile)
static constexpr int S_B = 9216;    // B region per buffer: 64*36*4
static constexpr int SMEM_TOTAL = 2 * (S_A + S_B);   // 55296 -> 3 CTAs/SM (165888 B)

__device__ __forceinline__ uint32_t smem_u32(const void* p) {
    uint32_t a;
    asm("{ .reg .u64 t; cvta.to.shared.u64 t, %1; cvt.u32.u64 %0, t; }" : "=r"(a) : "l"(p));
    return a;
}
__device__ __forceinline__ float f2tf32f(float f) {
    uint32_t r;
    asm("cvt.rna.tf32.f32 %0, %1;" : "=r"(r) : "f"(f));
    return __uint_as_float(r);
}
#define CP_ASYNC16(dst32, src) \
    asm volatile("cp.async.cg.shared.global [%0], [%1], 16;" :: "r"(dst32), "l"(src))
#define CP_COMMIT() asm volatile("cp.async.commit_group;" ::: "memory")
#define CP_WAIT0()  asm volatile("cp.async.wait_group 0;" ::: "memory")
#define STS128(addr, v) \
    asm volatile("st.shared.v4.b32 [%0], {%1,%2,%3,%4};" \
                 :: "r"(addr), "f"(v.x), "f"(v.y), "f"(v.z), "f"(v.w) : "memory")

__device__ __forceinline__ void mma_tf32(float* d, uint32_t a0, uint32_t a1,
                                         uint32_t a2, uint32_t a3,
                                         uint32_t b0, uint32_t b1) {
    asm volatile(
        "mma.sync.aligned.m16n8k8.row.col.f32.tf32.tf32.f32 "
        "{%0,%1,%2,%3}, {%4,%5,%6,%7}, {%8,%9}, {%0,%1,%2,%3};"
        : "+f"(d[0]), "+f"(d[1]), "+f"(d[2]), "+f"(d[3])
        : "r"(a0), "r"(a1), "r"(a2), "r"(a3), "r"(b0), "r"(b1));
}

// Pre-pass: round W to tf32 once (natural [d][e] layout)
__global__ void w_round_kernel(const float* __restrict__ W) {
    const int i = blockIdx.x * 256 + threadIdx.x;   // 32768 float4
    float4 v = reinterpret_cast<const float4*>(W)[i];
    v.x = f2tf32f(v.x); v.y = f2tf32f(v.y); v.z = f2tf32f(v.z); v.w = f2tf32f(v.w);
    reinterpret_cast<float4*>(g_Wtf32)[i] = v;
}

// ============================ Stage 1 ============================
// CTA tile: 128 e-rows x 64 k-cols.  Warps: 4 along e (32 each) x 2 along k (32 each).
__global__ void __launch_bounds__(256, 3)
slam_stage1(const float* __restrict__ x_aux, const float* __restrict__ bias) {
    extern __shared__ __align__(16) char smem[];
    const uint32_t sb = smem_u32(smem);
    const int tid = threadIdx.x, wid = tid >> 5, lid = tid & 31;
    const int g = lid >> 2, tg = lid & 3;
    const int warp_m = (wid & 3) * 32;    // e within CTA
    const int warp_n = (wid >> 2) * 32;   // k within CTA
    const int t = blockIdx.z, m0 = blockIdx.y * 128, n0 = blockIdx.x * 64;

    const float* Bsrc = x_aux + (size_t)t * 256;    // rows k, stride 32768
    float* C = g_scratch + (size_t)t * 512 * 256;   // [e][k]

    const uint32_t aoff[2] = {sb, sb + S_A};
    const uint32_t boff[2] = {sb + 2 * S_A, sb + 2 * S_A + S_B};

    // cp.async: W tile [32 d][128 e], ld=136 floats (544 B rows)
    auto cpasync_tile = [&](int kt, int buf) {
#pragma unroll
        for (int i = 0; i < 4; ++i) {
            const int idx = tid + i * 256;          // 0..1023
            const int row = idx >> 5, ch = idx & 31;
            CP_ASYNC16(aoff[buf] + row * 544 + ch * 16,
                       g_Wtf32 + (size_t)(kt * 32 + row) * 512 + m0 + ch * 4);
        }
    };
    // staged LDG: x_aux tile [64 k][32 d] -> 2 float4 per thread
    const int srow = tid >> 3, sch = tid & 7;       // srow 0..31
    auto ldg_tile = [&](int kt, float4 (&r)[2]) {
#pragma unroll
        for (int i = 0; i < 2; ++i)
            r[i] = *reinterpret_cast<const float4*>(
                Bsrc + (size_t)(n0 + srow + i * 32) * (128 * 256) + kt * 32 + sch * 4);
    };
    auto sts_tile = [&](float4 (&r)[2], int buf) {
        const uint32_t base = boff[buf] + srow * 144 + sch * 16;
#pragma unroll
        for (int i = 0; i < 2; ++i) {
            float4 v = r[i];
            v.x = f2tf32f(v.x); v.y = f2tf32f(v.y);
            v.z = f2tf32f(v.z); v.w = f2tf32f(v.w);
            STS128(base + i * 32 * 144, v);
        }
    };

    float acc[2][4][4];
#pragma unroll
    for (int mi = 0; mi < 2; ++mi)
#pragma unroll
        for (int nj = 0; nj < 4; ++nj)
#pragma unroll
            for (int q = 0; q < 4; ++q) acc[mi][nj][q] = 0.0f;

    auto compute_tile = [&](int buf) {
        const float* As = (const float*)(smem + (buf ? S_A : 0));
        const float* Bs = (const float*)(smem + 2 * S_A + (buf ? S_B : 0));
#pragma unroll
        for (int ks = 0; ks < 4; ++ks) {
            const int k8 = ks * 8;
            uint32_t af[2][4], bf[4][2];
#pragma unroll
            for (int mi = 0; mi < 2; ++mi) {
                const int e_ = warp_m + 16 * mi + g;
                const int d_ = k8 + tg;
                af[mi][0] = __float_as_uint(As[d_ * 136 + e_]);
                af[mi][1] = __float_as_uint(As[d_ * 136 + e_ + 8]);
                af[mi][2] = __float_as_uint(As[(d_ + 4) * 136 + e_]);
                af[mi][3] = __float_as_uint(As[(d_ + 4) * 136 + e_ + 8]);
            }
#pragma unroll
            for (int nj = 0; nj < 4; ++nj) {
                const int n_ = warp_n + 8 * nj + g;
                bf[nj][0] = __float_as_uint(Bs[n_ * 36 + k8 + tg]);
                bf[nj][1] = __float_as_uint(Bs[n_ * 36 + k8 + tg + 4]);
            }
#pragma unroll
            for (int mi = 0; mi < 2; ++mi)
#pragma unroll
                for (int nj = 0; nj < 4; ++nj)
                    mma_tf32(acc[mi][nj], af[mi][0], af[mi][1], af[mi][2], af[mi][3],
                             bf[nj][0], bf[nj][1]);
        }
    };

    float4 stage_regs[2];
    cpasync_tile(0, 0);
    CP_COMMIT();
    ldg_tile(0, stage_regs);
    CP_WAIT0();
    sts_tile(stage_regs, 0);
    __syncthreads();

    int buf = 0;
#pragma unroll 1
    for (int kt = 0; kt < 8; ++kt) {
        if (kt < 7) {
            cpasync_tile(kt + 1, buf ^ 1);
            CP_COMMIT();
            ldg_tile(kt + 1, stage_regs);
        }
        compute_tile(buf);
        if (kt < 7) {
            CP_WAIT0();
            sts_tile(stage_regs, buf ^ 1);
            __syncthreads();
        }
        buf ^= 1;
    }

    // epilogue: bias + relu + tf32-round, float2 stores into [e][k]
#pragma unroll
    for (int mi = 0; mi < 2; ++mi) {
        const int r0 = m0 + warp_m + 16 * mi + g;   // e rows
        const int r1 = r0 + 8;
        const float bv0 = bias[r0], bv1 = bias[r1];
#pragma unroll
        for (int nj = 0; nj < 4; ++nj) {
            const int col = n0 + warp_n + 8 * nj + 2 * tg;   // k cols
            float2 v0, v1;
            v0.x = f2tf32f(fmaxf(acc[mi][nj][0] + bv0, 0.0f));
            v0.y = f2tf32f(fmaxf(acc[mi][nj][1] + bv0, 0.0f));
            v1.x = f2tf32f(fmaxf(acc[mi][nj][2] + bv1, 0.0f));
            v1.y = f2tf32f(fmaxf(acc[mi][nj][3] + bv1, 0.0f));
            *reinterpret_cast<float2*>(C + (size_t)r0 * 256 + col) = v0;
            *reinterpret_cast<float2*>(C + (size_t)r1 * 256 + col) = v1;
        }
    }
}

// ============================ Stage 2 ============================
// CTA tile: 128 m-rows x 64 e-cols.  Warps: 4 along m x 2 along e.
__global__ void __launch_bounds__(256, 3)
slam_stage2(const float* __restrict__ x_main, float* __restrict__ out) {
    extern __shared__ __align__(16) char smem[];
    const uint32_t sb = smem_u32(smem);
    const int tid = threadIdx.x, wid = tid >> 5, lid = tid & 31;
    const int g = lid >> 2, tg = lid & 3;
    const int warp_m = (wid & 3) * 32;
    const int warp_n = (wid >> 2) * 32;
    const int t = blockIdx.z, m0 = blockIdx.y * 128, n0 = blockIdx.x * 64;

    const float* A = x_main + (size_t)t * 512 * 256;
    const float* Bsrc = g_scratch + (size_t)t * 512 * 256;
    float* C = out + (size_t)t * 512 * 512;

    const uint32_t aoff[2] = {sb, sb + S_A};
    const uint32_t boff[2] = {sb + 2 * S_A, sb + 2 * S_A + S_B};

    // cp.async: scratch tile [64 e][32 k], ld=36 (pre-rounded tf32)
    auto cpasync_tile = [&](int kt, int buf) {
#pragma unroll
        for (int i = 0; i < 2; ++i) {
            const int idx = tid + i * 256;          // 0..511
            const int row = idx >> 3, ch = idx & 7;
            CP_ASYNC16(boff[buf] + row * 144 + ch * 16,
                       Bsrc + (size_t)(n0 + row) * 256 + kt * 32 + ch * 4);
        }
    };
    // staged LDG: x_main tile [128 m][32 k] -> 4 float4 per thread
    const int srow = tid >> 3, sch = tid & 7;
    auto ldg_tile = [&](int kt, float4 (&r)[4]) {
#pragma unroll
        for (int i = 0; i < 4; ++i)
            r[i] = *reinterpret_cast<const float4*>(
                A + (size_t)(m0 + srow + i * 32) * 256 + kt * 32 + sch * 4);
    };
    auto sts_tile = [&](float4 (&r)[4], int buf) {
        const uint32_t base = aoff[buf] + srow * 144 + sch * 16;
#pragma unroll
        for (int i = 0; i < 4; ++i) {
            float4 v = r[i];
            v.x = f2tf32f(v.x); v.y = f2tf32f(v.y);
            v.z = f2tf32f(v.z); v.w = f2tf32f(v.w);
            STS128(base + i * 32 * 144, v);
        }
    };

    float acc[2][4][4];
#pragma unroll
    for (int mi = 0; mi < 2; ++mi)
#pragma unroll
        for (int nj = 0; nj < 4; ++nj)
#pragma unroll
            for (int q = 0; q < 4; ++q) acc[mi][nj][q] = 0.0f;

    auto compute_tile = [&](int buf) {
        const float* As = (const float*)(smem + (buf ? S_A : 0));
        const float* Bs = (const float*)(smem + 2 * S_A + (buf ? S_B : 0));
#pragma unroll
        for (int ks = 0; ks < 4; ++ks) {
            const int k8 = ks * 8;
            uint32_t af[2][4], bf[4][2];
#pragma unroll
            for (int mi = 0; mi < 2; ++mi) {
                const int r_ = warp_m + 16 * mi + g;
                const int c_ = k8 + tg;
                af[mi][0] = __float_as_uint(As[r_ * 36 + c_]);
                af[mi][1] = __float_as_uint(As[(r_ + 8) * 36 + c_]);
                af[mi][2] = __float_as_uint(As[r_ * 36 + c_ + 4]);
                af[mi][3] = __float_as_uint(As[(r_ + 8) * 36 + c_ + 4]);
            }
#pragma unroll
            for (int nj = 0; nj < 4; ++nj) {
                const int n_ = warp_n + 8 * nj + g;
                bf[nj][0] = __float_as_uint(Bs[n_ * 36 + k8 + tg]);
                bf[nj][1] = __float_as_uint(Bs[n_ * 36 + k8 + tg + 4]);
            }
#pragma unroll
            for (int mi = 0; mi < 2; ++mi)
#pragma unroll
                for (int nj = 0; nj < 4; ++nj)
                    mma_tf32(acc[mi][nj], af[mi][0], af[mi][1], af[mi][2], af[mi][3],
                             bf[nj][0], bf[nj][1]);
        }
    };

    float4 stage_regs[4];
    cpasync_tile(0, 0);
    CP_COMMIT();
    ldg_tile(0, stage_regs);
    CP_WAIT0();
    sts_tile(stage_regs, 0);
    __syncthreads();

    int buf = 0;
#pragma unroll 1
    for (int kt = 0; kt < 8; ++kt) {
        if (kt < 7) {
            cpasync_tile(kt + 1, buf ^ 1);
            CP_COMMIT();
            ldg_tile(kt + 1, stage_regs);
        }
        compute_tile(buf);
        if (kt < 7) {
            CP_WAIT0();
            sts_tile(stage_regs, buf ^ 1);
            __syncthreads();
        }
        buf ^= 1;
    }

    // epilogue: float2 stores
#pragma unroll
    for (int mi = 0; mi < 2; ++mi) {
        const int r0 = m0 + warp_m + 16 * mi + g;
        const int r1 = r0 + 8;
#pragma unroll
        for (int nj = 0; nj < 4; ++nj) {
            const int col = n0 + warp_n + 8 * nj + 2 * tg;
            float2 v0, v1;
            v0.x = acc[mi][nj][0]; v0.y = acc[mi][nj][1];
            v1.x = acc[mi][nj][2]; v1.y = acc[mi][nj][3];
            *reinterpret_cast<float2*>(C + (size_t)r0 * 512 + col) = v0;
            *reinterpret_cast<float2*>(C + (size_t)r1 * 512 + col) = v1;
        }
    }
}

extern "C" void kernel_launch(void* const* d_in, const int* in_sizes, int n_in,
                              void* d_out, int out_size) {
    const float* x_main = (const float*)d_in[0];  // [1,128,512,256]
    const float* x_aux  = (const float*)d_in[1];  // [256,128,256]
    const float* W      = (const float*)d_in[2];  // [256,512]
    const float* b      = (const float*)d_in[3];  // [512]
    float* out = (float*)d_out;                   // [128,512,512]

    cudaFuncSetAttribute(slam_stage1,
                         cudaFuncAttributeMaxDynamicSharedMemorySize, SMEM_TOTAL);
    cudaFuncSetAttribute(slam_stage2,
                         cudaFuncAttributeMaxDynamicSharedMemorySize, SMEM_TOTAL);

    // W -> tf32 (once per launch)
    w_round_kernel<<<128, 256>>>(W);
    // Stage 1: per-t  D[e(512) x k(256)] = W^T x_aux[.,t,.]^T (+bias, relu) -> scratch
    slam_stage1<<<dim3(4, 4, 128), 256, SMEM_TOTAL>>>(x_aux, b);
    // Stage 2: per-t  D[m(512) x e(512)] = x_main[t] . scratch[t]^T -> out
    slam_stage2<<<dim3(8, 4, 128), 256, SMEM_TOTAL>>>(x_main, out);
}